// round 9
// baseline (speedup 1.0000x reference)
#include <cuda_runtime.h>
#include <cuda_fp16.h>
#include <cstdint>

// Problem constants
#define NRES 768
#define TF   21
#define MSADIM 49
#define CZ   128
#define CM   256
#define MSA_OUT_ELEMS (512u*768u*256u)   // 100663296
#define TOT_ITEMS 15360                  // 5 * 3072
#define GRID_U 592                       // 4 CTAs per SM

// ---------------- device scratch ----------------
__device__ float  g_tfi[NRES * CZ];
__device__ float  g_tfj[NRES * CZ];
__device__ float  g_comb[NRES * CM];
__device__ __half g_wh[48 * CM];         // fp16 weights k=0..47
__device__ float  g_w48[CM];             // fp32 weight row k=48

// ---------------- smem layout per CTA (bytes) ----------------
// W    [48][264h] stride 528   @ 0       (25344)
// raw0 32x49 f32               @ 25344   (6272)
// raw1                         @ 31616   (6272)
// w48  fp32[256]               @ 37888   (1024)
// a48  fp32[32]                @ 38912   (128)
// A_hi [32][56h]  stride 112   @ 39040   (3584)
// A_lo                         @ 42624   (3584)
// stg  8 rows x 1056B          @ 46208   (8448)  -> 54656
#define W_STRIDE 528
#define A_STRIDE 112
#define OFF_W    0
#define OFF_RAW0 25344
#define OFF_RAW1 31616
#define OFF_W48  37888
#define OFF_A48  38912
#define OFF_AHI  39040
#define OFF_ALO  42624
#define OFF_STG  46208
#define STG_STRIDE 1056
#define U_SMEM   54656

// ---------------- helpers ----------------
__device__ __forceinline__ uint32_t smem_u32(const void* p) {
    uint32_t a;
    asm("{ .reg .u64 t; cvta.to.shared.u64 t, %1; cvt.u32.u64 %0, t; }" : "=r"(a) : "l"(p));
    return a;
}
__device__ __forceinline__ void cp16(uint32_t dst, const void* src) {
    asm volatile("cp.async.cg.shared.global [%0], [%1], 16;" :: "r"(dst), "l"(src) : "memory");
}
__device__ __forceinline__ void cp_commit() {
    asm volatile("cp.async.commit_group;" ::: "memory");
}
__device__ __forceinline__ void cp_wait_all() {
    asm volatile("cp.async.wait_group 0;" ::: "memory");
}

#define LDSM_X4(r, addr) \
    asm volatile("ldmatrix.sync.aligned.m8n8.x4.shared.b16 {%0,%1,%2,%3}, [%4];" \
                 : "=r"((r)[0]), "=r"((r)[1]), "=r"((r)[2]), "=r"((r)[3]) : "r"(addr))
#define LDSM_X4T(r, addr) \
    asm volatile("ldmatrix.sync.aligned.m8n8.x4.trans.shared.b16 {%0,%1,%2,%3}, [%4];" \
                 : "=r"((r)[0]), "=r"((r)[1]), "=r"((r)[2]), "=r"((r)[3]) : "r"(addr))
#define MMAF16(d, a, b0v, b1v) \
    asm volatile("mma.sync.aligned.m16n8k16.row.col.f32.f16.f16.f32 " \
                 "{%0,%1,%2,%3}, {%4,%5,%6,%7}, {%8,%9}, {%0,%1,%2,%3};" \
                 : "+f"((d)[0]), "+f"((d)[1]), "+f"((d)[2]), "+f"((d)[3]) \
                 : "r"((a)[0]), "r"((a)[1]), "r"((a)[2]), "r"((a)[3]), \
                   "r"(b0v), "r"(b1v))

// ---------------- kernel 1: precompute ----------------
__global__ void __launch_bounds__(256) pre_kernel(
        const float* __restrict__ tf,
        const float* __restrict__ wzi, const float* __restrict__ bzi,
        const float* __restrict__ wzj, const float* __restrict__ bzj,
        const float* __restrict__ wm,  const float* __restrict__ bm,
        const float* __restrict__ bmsa, const float* __restrict__ wmsa) {
    int c = threadIdx.x;
    if (blockIdx.x >= 96) {
        int k = blockIdx.x - 96;   // 0..48
        float v = wmsa[k * CM + c];
        if (k < 48) g_wh[k * CM + c] = __float2half_rn(v);
        else        g_w48[c] = v;
        return;
    }
    __shared__ float swm[TF * CM];
    __shared__ float swi[TF * CZ];
    __shared__ float swj[TF * CZ];
    __shared__ float st[8 * TF];

    for (int g = c; g < TF * CM; g += 256) swm[g] = wm[g];
    for (int g = c; g < TF * CZ; g += 256) { swi[g] = wzi[g]; swj[g] = wzj[g]; }
    int i0 = blockIdx.x * 8;
    for (int g = c; g < 8 * TF; g += 256) st[g] = tf[i0 * TF + g];
    __syncthreads();

    float bmv = bm[c] + bmsa[c];
    float bzi_v = (c < CZ) ? bzi[c] : 0.0f;
    float bzj_v = (c < CZ) ? bzj[c] : 0.0f;

#pragma unroll 1
    for (int r = 0; r < 8; r++) {
        const float* t = st + r * TF;
        float am = bmv;
#pragma unroll
        for (int k = 0; k < TF; k++) am += t[k] * swm[k * CM + c];
        g_comb[(i0 + r) * CM + c] = am;

        if (c < CZ) {
            float ai = bzi_v;
            float aj = bzj_v;
#pragma unroll
            for (int k = 0; k < TF; k++) {
                float tv = t[k];
                ai += tv * swi[k * CZ + c];
                aj += tv * swj[k * CZ + c];
            }
            g_tfi[(i0 + r) * CZ + c] = ai;
            g_tfj[(i0 + r) * CZ + c] = aj;
        }
    }
}

// ---------------- kernel 2: unified persistent msa + pair ----------------
__global__ void __launch_bounds__(256, 4) uni_kernel(const float* __restrict__ msa,
                                                     const int* __restrict__ res,
                                                     const int* __restrict__ sym,
                                                     const int* __restrict__ asym,
                                                     const int* __restrict__ ent,
                                                     const float* __restrict__ w_rel,
                                                     const float* __restrict__ b_rel,
                                                     float* __restrict__ out) {
    extern __shared__ char smem[];
    uint32_t sb = smem_u32(smem);
    int tid = threadIdx.x;
    int lane = tid & 31;
    int bid = blockIdx.x;
    float* msa_out  = out;
    float* pair_out = out + MSA_OUT_ELEMS;

    // stage weights + w48 once
    for (int g = tid; g < 1536; g += 256) {
        int row = g >> 5;
        int c = g & 31;
        cp16(sb + OFF_W + row * W_STRIDE + c * 16, (const char*)g_wh + row * 512 + c * 16);
    }
    if (tid < 64) cp16(sb + OFF_W48 + tid * 16, (const char*)g_w48 + tid * 16);
    // prefetch first msa tile raw
    {
        int wf = bid;
        while (wf < TOT_ITEMS && (wf % 5) == 4) wf += GRID_U;
        if (wf < TOT_ITEMS) {
            int m = (wf / 5) * 4 + (wf % 5);
            const char* src = (const char*)msa + (long)m * 6272;
            for (int g = tid; g < 392; g += 256)
                cp16(sb + OFF_RAW0 + g * 16, src + g * 16);
        }
    }
    cp_commit();

    int wid = tid >> 5;
    int warp_m = wid & 1;          // 2 m-warps of 16 rows
    int warp_n = wid >> 1;         // 4 n-warps of 64 channels
    uint32_t aoff = (uint32_t)((warp_m * 16 + (lane & 15)) * A_STRIDE + (lane >> 4) * 16);
    uint32_t boff = (uint32_t)(((lane & 7) + ((lane >> 3) & 1) * 8) * W_STRIDE +
                               (warp_n * 64 + (lane >> 4) * 8) * 2);
    uint32_t b_base = sb + OFF_W + boff;
    uint32_t ahi_base = sb + OFF_AHI + aoff;
    uint32_t alo_base = sb + OFF_ALO + aoff;
    int qr = lane >> 2;
    int qc = (lane & 3) * 2;
    int msa_cnt = 0;

    const float* s_w48f = (const float*)(smem + OFF_W48);
    const float* s_a48f = (const float*)(smem + OFF_A48);

    for (int w = bid; w < TOT_ITEMS; w += GRID_U) {
        if ((w % 5) != 4) {
            // ================= msa tile (32 rows x 256 ch) =================
            int t = (w / 5) * 4 + (w % 5);
            uint32_t raw_cur = (msa_cnt & 1) ? OFF_RAW1 : OFF_RAW0;
            uint32_t raw_nxt = (msa_cnt & 1) ? OFF_RAW0 : OFF_RAW1;
            msa_cnt++;
            const float* rawf = (const float*)(smem + raw_cur);

            cp_wait_all();
            __syncthreads();   // raw ready; prev tile done

            // convert raw -> A hi/lo fp16 (k<48); stash a48 column
            for (int g = tid; g < 768; g += 256) {
                int row = g / 24;
                int p = g - row * 24;
                float a0 = rawf[row * 49 + 2 * p];
                float a1 = rawf[row * 49 + 2 * p + 1];
                __half h0 = __float2half_rn(a0);
                __half h1 = __float2half_rn(a1);
                __half l0 = __float2half_rn(a0 - __half2float(h0));
                __half l1 = __float2half_rn(a1 - __half2float(h1));
                uint32_t o = row * A_STRIDE + p * 4;
                *(__half2*)(smem + OFF_AHI + o) = __halves2half2(h0, h1);
                *(__half2*)(smem + OFF_ALO + o) = __halves2half2(l0, l1);
            }
            if (tid < 32) ((float*)(smem + OFF_A48))[tid] = rawf[tid * 49 + 48];
            __syncthreads();   // A ready

            // prefetch next msa tile's raw (overlaps MMA)
            {
                int wn = w + GRID_U;
                while (wn < TOT_ITEMS && (wn % 5) == 4) wn += GRID_U;
                if (wn < TOT_ITEMS) {
                    int m2 = (wn / 5) * 4 + (wn % 5);
                    const char* src = (const char*)msa + (long)m2 * 6272;
                    for (int g = tid; g < 392; g += 256)
                        cp16(sb + raw_nxt + g * 16, src + g * 16);
                }
            }
            cp_commit();

            // MMA: 3 k-steps, 2 terms; B loaded per 16-ch group to cap live regs
            float d[8][4];
#pragma unroll
            for (int nt = 0; nt < 8; nt++)
#pragma unroll
                for (int i = 0; i < 4; i++) d[nt][i] = 0.0f;

#pragma unroll
            for (int ks = 0; ks < 3; ks++) {
                uint32_t ak = ks * 32;
                uint32_t bk = ks * 16 * W_STRIDE;

                uint32_t ah[4], al[4];
                LDSM_X4(ah, ahi_base + ak);
                LDSM_X4(al, alo_base + ak);

#pragma unroll
                for (int g = 0; g < 4; g++) {
                    uint32_t bh[4];
                    LDSM_X4T(bh, b_base + bk + g * 32);
#pragma unroll
                    for (int sub = 0; sub < 2; sub++) {
                        int nt = g * 2 + sub;
                        MMAF16(d[nt], ah, bh[sub * 2], bh[sub * 2 + 1]);
                        MMAF16(d[nt], al, bh[sub * 2], bh[sub * 2 + 1]);
                    }
                }
            }

            // ---- epilogue: 4 quarter passes of 8 rows, coalesced ----
            long rowbase = (long)t * 32;
            int n0 = (int)(rowbase % NRES);
#pragma unroll
            for (int p = 0; p < 4; p++) {
                if (warp_m == (p >> 1)) {
                    char* stg = smem + OFF_STG;
                    int chb = (warp_n * 64 + qc) * 4;
                    int half = p & 1;
#pragma unroll
                    for (int nt = 0; nt < 8; nt++) {
                        float2 v = half ? make_float2(d[nt][2], d[nt][3])
                                        : make_float2(d[nt][0], d[nt][1]);
                        *(float2*)(stg + qr * STG_STRIDE + chb + nt * 32) = v;
                    }
                }
                __syncthreads();
#pragma unroll
                for (int q = 0; q < 2; q++) {
                    int g = tid + q * 256;
                    int row = g >> 6;        // 0..7
                    int c4 = g & 63;
                    float4 v = *(const float4*)(smem + OFF_STG + row * STG_STRIDE + c4 * 16);
                    float4 w48v = *(const float4*)(s_w48f + c4 * 4);
                    int grow = p * 8 + row;
                    float a48v = s_a48f[grow];
                    float4 cb = __ldg((const float4*)(g_comb + (n0 + grow) * CM) + c4);
                    float4 o = make_float4(v.x + a48v * w48v.x + cb.x,
                                           v.y + a48v * w48v.y + cb.y,
                                           v.z + a48v * w48v.z + cb.z,
                                           v.w + a48v * w48v.w + cb.w);
                    __stcs((float4*)(msa_out + (rowbase + grow) * (long)CM) + c4, o);
                }
                __syncthreads();
            }
        } else {
            // ================= pair tile =================
            int p = w / 5;
            int i = p >> 2;
            int jstart = (p & 3) * 192;
            int jl = tid >> 5;   // 8 j-lanes

            int res_i  = __ldg(res + i);
            int sym_i  = __ldg(sym + i);
            int asym_i = __ldg(asym + i);
            int ent_i  = __ldg(ent + i);

            float4 b4 = __ldg(((const float4*)b_rel) + lane);
            float4 ti = __ldg(((const float4*)(g_tfi + i * CZ)) + lane);
            float4 base4 = make_float4(b4.x + ti.x, b4.y + ti.y, b4.z + ti.z, b4.w + ti.w);
            const float4* W4 = (const float4*)w_rel;
            float4 w66 = __ldg(W4 + 66 * 32 + lane);

#pragma unroll 4
            for (int it = 0; it < 24; it++) {
                int j = jstart + it * 8 + jl;
                int rj = __ldg(res + j), sj = __ldg(sym + j), aj = __ldg(asym + j);

                int off = res_i - rj + 32;
                off = min(max(off, 0), 64);
                int pos = (asym_i == aj) ? off : 65;

                int ed = ent_i - sj;
                float entf = (float)ed;

                int cc = sym_i - sj + 2;
                cc = min(max(cc, 0), 4);
                int chain = (ed != 0) ? cc : 5;

                float4 wp = __ldg(W4 + pos * 32 + lane);
                float4 wc = __ldg(W4 + (67 + chain) * 32 + lane);
                float4 tj = __ldg(((const float4*)(g_tfj + j * CZ)) + lane);

                float4 o;
                o.x = base4.x + wp.x + entf * w66.x + wc.x + tj.x;
                o.y = base4.y + wp.y + entf * w66.y + wc.y + tj.y;
                o.z = base4.z + wp.z + entf * w66.z + wc.z + tj.z;
                o.w = base4.w + wp.w + entf * w66.w + wc.w + tj.w;

                __stcs(((float4*)(pair_out + ((size_t)i * NRES + j) * CZ)) + lane, o);
            }
        }
    }
}

// ---------------- launch ----------------
extern "C" void kernel_launch(void* const* d_in, const int* in_sizes, int n_in,
                              void* d_out, int out_size) {
    const float* tf     = (const float*)d_in[0];
    const float* msa    = (const float*)d_in[1];
    const int*   res    = (const int*)d_in[2];
    const int*   sym    = (const int*)d_in[3];
    const int*   asym   = (const int*)d_in[4];
    const int*   ent    = (const int*)d_in[5];
    const float* w_zi   = (const float*)d_in[6];
    const float* b_zi   = (const float*)d_in[7];
    const float* w_zj   = (const float*)d_in[8];
    const float* b_zj   = (const float*)d_in[9];
    const float* w_m    = (const float*)d_in[10];
    const float* b_m    = (const float*)d_in[11];
    const float* w_msa  = (const float*)d_in[12];
    const float* b_msa  = (const float*)d_in[13];
    const float* w_rel  = (const float*)d_in[14];
    const float* b_rel  = (const float*)d_in[15];

    cudaFuncSetAttribute(uni_kernel, cudaFuncAttributeMaxDynamicSharedMemorySize, U_SMEM);

    pre_kernel<<<96 + 49, 256>>>(tf, w_zi, b_zi, w_zj, b_zj, w_m, b_m, b_msa, w_msa);
    uni_kernel<<<GRID_U, 256, U_SMEM>>>(msa, res, sym, asym, ent, w_rel, b_rel,
                                        (float*)d_out);
}

// round 10
// speedup vs baseline: 1.1371x; 1.1371x over previous
#include <cuda_runtime.h>
#include <cuda_fp16.h>
#include <cstdint>

// Problem constants
#define NRES 768
#define TF   21
#define MSADIM 49
#define CZ   128
#define CM   256
#define MSA_OUT_ELEMS (512u*768u*256u)   // 100663296
#define TOT_ITEMS 15360                  // 5 * 3072
#define GRID_U 444                       // 3 CTAs per SM

// ---------------- device scratch ----------------
__device__ float  g_tfi[NRES * CZ];
__device__ float  g_tfj[NRES * CZ];
__device__ float  g_comb[NRES * CM];
__device__ __half g_wh[48 * CM];         // fp16 weights k=0..47
__device__ float  g_w48[CM];             // fp32 weight row k=48

// ---------------- smem layout per CTA (bytes) ----------------
// W    [48][264h] stride 528   @ 0       (25344)
// raw0 32x49 f32               @ 25344   (6272)
// raw1                         @ 31616   (6272)
// w48  fp32[256]               @ 37888   (1024)
// A_hi [32][56h]  stride 112   @ 38912   (3584)
// A_lo                         @ 42496   (3584)
// stg  16 rows x 1056B         @ 46080   (16896) -> 62976
#define W_STRIDE 528
#define A_STRIDE 112
#define OFF_W    0
#define OFF_RAW0 25344
#define OFF_RAW1 31616
#define OFF_W48  37888
#define OFF_AHI  38912
#define OFF_ALO  42496
#define OFF_STG  46080
#define STG_STRIDE 1056
#define U_SMEM   62976

// ---------------- helpers ----------------
__device__ __forceinline__ uint32_t smem_u32(const void* p) {
    uint32_t a;
    asm("{ .reg .u64 t; cvta.to.shared.u64 t, %1; cvt.u32.u64 %0, t; }" : "=r"(a) : "l"(p));
    return a;
}
__device__ __forceinline__ void cp16(uint32_t dst, const void* src) {
    asm volatile("cp.async.cg.shared.global [%0], [%1], 16;" :: "r"(dst), "l"(src) : "memory");
}
__device__ __forceinline__ void cp_commit() {
    asm volatile("cp.async.commit_group;" ::: "memory");
}
__device__ __forceinline__ void cp_wait_all() {
    asm volatile("cp.async.wait_group 0;" ::: "memory");
}

#define LDSM_X4(r, addr) \
    asm volatile("ldmatrix.sync.aligned.m8n8.x4.shared.b16 {%0,%1,%2,%3}, [%4];" \
                 : "=r"((r)[0]), "=r"((r)[1]), "=r"((r)[2]), "=r"((r)[3]) : "r"(addr))
#define LDSM_X4T(r, addr) \
    asm volatile("ldmatrix.sync.aligned.m8n8.x4.trans.shared.b16 {%0,%1,%2,%3}, [%4];" \
                 : "=r"((r)[0]), "=r"((r)[1]), "=r"((r)[2]), "=r"((r)[3]) : "r"(addr))
#define MMAF16(d, a, b0v, b1v) \
    asm volatile("mma.sync.aligned.m16n8k16.row.col.f32.f16.f16.f32 " \
                 "{%0,%1,%2,%3}, {%4,%5,%6,%7}, {%8,%9}, {%0,%1,%2,%3};" \
                 : "+f"((d)[0]), "+f"((d)[1]), "+f"((d)[2]), "+f"((d)[3]) \
                 : "r"((a)[0]), "r"((a)[1]), "r"((a)[2]), "r"((a)[3]), \
                   "r"(b0v), "r"(b1v))

// ---------------- kernel 1: precompute ----------------
__global__ void __launch_bounds__(256) pre_kernel(
        const float* __restrict__ tf,
        const float* __restrict__ wzi, const float* __restrict__ bzi,
        const float* __restrict__ wzj, const float* __restrict__ bzj,
        const float* __restrict__ wm,  const float* __restrict__ bm,
        const float* __restrict__ bmsa, const float* __restrict__ wmsa) {
    int c = threadIdx.x;
    if (blockIdx.x >= 96) {
        int k = blockIdx.x - 96;   // 0..48
        float v = wmsa[k * CM + c];
        if (k < 48) g_wh[k * CM + c] = __float2half_rn(v);
        else        g_w48[c] = v;
        return;
    }
    __shared__ float swm[TF * CM];
    __shared__ float swi[TF * CZ];
    __shared__ float swj[TF * CZ];
    __shared__ float st[8 * TF];

    for (int g = c; g < TF * CM; g += 256) swm[g] = wm[g];
    for (int g = c; g < TF * CZ; g += 256) { swi[g] = wzi[g]; swj[g] = wzj[g]; }
    int i0 = blockIdx.x * 8;
    for (int g = c; g < 8 * TF; g += 256) st[g] = tf[i0 * TF + g];
    __syncthreads();

    float bmv = bm[c] + bmsa[c];
    float bzi_v = (c < CZ) ? bzi[c] : 0.0f;
    float bzj_v = (c < CZ) ? bzj[c] : 0.0f;

#pragma unroll 1
    for (int r = 0; r < 8; r++) {
        const float* t = st + r * TF;
        float am = bmv;
#pragma unroll
        for (int k = 0; k < TF; k++) am += t[k] * swm[k * CM + c];
        g_comb[(i0 + r) * CM + c] = am;

        if (c < CZ) {
            float ai = bzi_v;
            float aj = bzj_v;
#pragma unroll
            for (int k = 0; k < TF; k++) {
                float tv = t[k];
                ai += tv * swi[k * CZ + c];
                aj += tv * swj[k * CZ + c];
            }
            g_tfi[(i0 + r) * CZ + c] = ai;
            g_tfj[(i0 + r) * CZ + c] = aj;
        }
    }
}

// ---------------- kernel 2: unified persistent msa + pair ----------------
// Warp layout: 8 warps, each m32 x n32 (ch = wid*32..+31). B fragments are
// loaded ONCE into registers (invariant across tiles) and stay resident.
__global__ void __launch_bounds__(256, 3) uni_kernel(const float* __restrict__ msa,
                                                     const int* __restrict__ res,
                                                     const int* __restrict__ sym,
                                                     const int* __restrict__ asym,
                                                     const int* __restrict__ ent,
                                                     const float* __restrict__ w_rel,
                                                     const float* __restrict__ b_rel,
                                                     float* __restrict__ out) {
    extern __shared__ char smem[];
    uint32_t sb = smem_u32(smem);
    int tid = threadIdx.x;
    int lane = tid & 31;
    int wid = tid >> 5;
    int bid = blockIdx.x;
    float* msa_out  = out;
    float* pair_out = out + MSA_OUT_ELEMS;

    // stage weights + w48 once
    for (int g = tid; g < 1536; g += 256) {
        int row = g >> 5;
        int c = g & 31;
        cp16(sb + OFF_W + row * W_STRIDE + c * 16, (const char*)g_wh + row * 512 + c * 16);
    }
    if (tid < 64) cp16(sb + OFF_W48 + tid * 16, (const char*)g_w48 + tid * 16);
    // prefetch first msa tile raw
    {
        int wf = bid;
        while (wf < TOT_ITEMS && (wf % 5) == 4) wf += GRID_U;
        if (wf < TOT_ITEMS) {
            int m = (wf / 5) * 4 + (wf % 5);
            const char* src = (const char*)msa + (long)m * 6272;
            for (int g = tid; g < 392; g += 256)
                cp16(sb + OFF_RAW0 + g * 16, src + g * 16);
        }
    }
    cp_commit();

    // per-thread ldmatrix addresses
    uint32_t aoff = (uint32_t)((lane & 15) * A_STRIDE + (lane >> 4) * 16);
    uint32_t ahi_base = sb + OFF_AHI + aoff;
    uint32_t alo_base = sb + OFF_ALO + aoff;
    uint32_t boff = (uint32_t)(((lane & 7) + ((lane >> 3) & 1) * 8) * W_STRIDE +
                               (wid * 32 + (lane >> 4) * 8) * 2);
    uint32_t b_base = sb + OFF_W + boff;
    int qr = lane >> 2;
    int qc = (lane & 3) * 2;
    int msa_cnt = 0;

    const float* s_w48f = (const float*)(smem + OFF_W48);

    // ---- load B fragments ONCE (weights are tile-invariant) ----
    cp_wait_all();
    __syncthreads();
    uint32_t bfr[3][8];
#pragma unroll
    for (int ks = 0; ks < 3; ks++) {
        LDSM_X4T(&bfr[ks][0], b_base + ks * 16 * W_STRIDE);
        LDSM_X4T(&bfr[ks][4], b_base + ks * 16 * W_STRIDE + 32);  // +16 ch
    }

    for (int w = bid; w < TOT_ITEMS; w += GRID_U) {
        if ((w % 5) != 4) {
            // ================= msa tile (32 rows x 256 ch) =================
            int t = (w / 5) * 4 + (w % 5);
            uint32_t raw_cur = (msa_cnt & 1) ? OFF_RAW1 : OFF_RAW0;
            uint32_t raw_nxt = (msa_cnt & 1) ? OFF_RAW0 : OFF_RAW1;
            msa_cnt++;
            const float* rawf = (const float*)(smem + raw_cur);

            cp_wait_all();
            __syncthreads();   // raw ready; prev tile done

            // convert raw -> A hi/lo fp16 (k<48)
            for (int g = tid; g < 768; g += 256) {
                int row = g / 24;
                int p = g - row * 24;
                float a0 = rawf[row * 49 + 2 * p];
                float a1 = rawf[row * 49 + 2 * p + 1];
                __half h0 = __float2half_rn(a0);
                __half h1 = __float2half_rn(a1);
                __half l0 = __float2half_rn(a0 - __half2float(h0));
                __half l1 = __float2half_rn(a1 - __half2float(h1));
                uint32_t o = row * A_STRIDE + p * 4;
                *(__half2*)(smem + OFF_AHI + o) = __halves2half2(h0, h1);
                *(__half2*)(smem + OFF_ALO + o) = __halves2half2(l0, l1);
            }
            __syncthreads();   // A ready

            // prefetch next msa tile's raw (overlaps MMA)
            {
                int wn = w + GRID_U;
                while (wn < TOT_ITEMS && (wn % 5) == 4) wn += GRID_U;
                if (wn < TOT_ITEMS) {
                    int m2 = (wn / 5) * 4 + (wn % 5);
                    const char* src = (const char*)msa + (long)m2 * 6272;
                    for (int g = tid; g < 392; g += 256)
                        cp16(sb + raw_nxt + g * 16, src + g * 16);
                }
            }
            cp_commit();

            // MMA: 3 k-steps, 2 terms; A through shared regs, B resident
            float d[2][4][4];
#pragma unroll
            for (int mt = 0; mt < 2; mt++)
#pragma unroll
                for (int nt = 0; nt < 4; nt++)
#pragma unroll
                    for (int i = 0; i < 4; i++) d[mt][nt][i] = 0.0f;

#pragma unroll
            for (int ks = 0; ks < 3; ks++) {
                uint32_t ak = ks * 32;
                uint32_t af[2][4];
                LDSM_X4(af[0], ahi_base + ak);
                LDSM_X4(af[1], ahi_base + 16 * A_STRIDE + ak);
#pragma unroll
                for (int mt = 0; mt < 2; mt++)
#pragma unroll
                    for (int nt = 0; nt < 4; nt++)
                        MMAF16(d[mt][nt], af[mt], bfr[ks][nt * 2], bfr[ks][nt * 2 + 1]);
                LDSM_X4(af[0], alo_base + ak);
                LDSM_X4(af[1], alo_base + 16 * A_STRIDE + ak);
#pragma unroll
                for (int mt = 0; mt < 2; mt++)
#pragma unroll
                    for (int nt = 0; nt < 4; nt++)
                        MMAF16(d[mt][nt], af[mt], bfr[ks][nt * 2], bfr[ks][nt * 2 + 1]);
            }

            // ---- epilogue: 2 half passes of 16 rows, coalesced ----
            long rowbase = (long)t * 32;
            int n0 = (int)(rowbase % NRES);
#pragma unroll
            for (int p = 0; p < 2; p++) {
                // stage this warp's 32 channels for rows p*16..p*16+15
                {
                    char* stg = smem + OFF_STG;
                    int chb = (wid * 32 + qc) * 4;
#pragma unroll
                    for (int nt = 0; nt < 4; nt++) {
                        *(float2*)(stg + qr * STG_STRIDE + chb + nt * 32) =
                            make_float2(d[p][nt][0], d[p][nt][1]);
                        *(float2*)(stg + (qr + 8) * STG_STRIDE + chb + nt * 32) =
                            make_float2(d[p][nt][2], d[p][nt][3]);
                    }
                }
                __syncthreads();
#pragma unroll
                for (int q = 0; q < 4; q++) {
                    int g = tid + q * 256;
                    int row = g >> 6;        // 0..15
                    int c4 = g & 63;
                    float4 v = *(const float4*)(smem + OFF_STG + row * STG_STRIDE + c4 * 16);
                    float4 w48v = *(const float4*)(s_w48f + c4 * 4);
                    int grow = p * 16 + row;
                    float a48v = rawf[grow * 49 + 48];
                    float4 cb = *(const float4*)(g_comb + (n0 + grow) * CM + c4 * 4);
                    float4 o = make_float4(v.x + a48v * w48v.x + cb.x,
                                           v.y + a48v * w48v.y + cb.y,
                                           v.z + a48v * w48v.z + cb.z,
                                           v.w + a48v * w48v.w + cb.w);
                    *(float4*)(msa_out + (rowbase + grow) * (long)CM + c4 * 4) = o;
                }
                __syncthreads();
            }
        } else {
            // ================= pair tile =================
            int p = w / 5;
            int i = p >> 2;
            int jstart = (p & 3) * 192;
            int jl = tid >> 5;   // 8 j-lanes

            int res_i  = __ldg(res + i);
            int sym_i  = __ldg(sym + i);
            int asym_i = __ldg(asym + i);
            int ent_i  = __ldg(ent + i);

            float4 b4 = ((const float4*)b_rel)[lane];
            float4 ti = ((const float4*)(g_tfi + i * CZ))[lane];
            float4 base4 = make_float4(b4.x + ti.x, b4.y + ti.y, b4.z + ti.z, b4.w + ti.w);
            const float4* W4 = (const float4*)w_rel;
            float4 w66 = W4[66 * 32 + lane];

#pragma unroll 4
            for (int it = 0; it < 24; it++) {
                int j = jstart + it * 8 + jl;
                int rj = __ldg(res + j), sj = __ldg(sym + j), aj = __ldg(asym + j);

                int off = res_i - rj + 32;
                off = min(max(off, 0), 64);
                int pos = (asym_i == aj) ? off : 65;

                int ed = ent_i - sj;
                float entf = (float)ed;

                int cc = sym_i - sj + 2;
                cc = min(max(cc, 0), 4);
                int chain = (ed != 0) ? cc : 5;

                float4 wp = W4[pos * 32 + lane];
                float4 wc = W4[(67 + chain) * 32 + lane];
                float4 tj = ((const float4*)(g_tfj + j * CZ))[lane];

                float4 o;
                o.x = base4.x + wp.x + entf * w66.x + wc.x + tj.x;
                o.y = base4.y + wp.y + entf * w66.y + wc.y + tj.y;
                o.z = base4.z + wp.z + entf * w66.z + wc.z + tj.z;
                o.w = base4.w + wp.w + entf * w66.w + wc.w + tj.w;

                ((float4*)(pair_out + ((size_t)i * NRES + j) * CZ))[lane] = o;
            }
        }
    }
}

// ---------------- launch ----------------
extern "C" void kernel_launch(void* const* d_in, const int* in_sizes, int n_in,
                              void* d_out, int out_size) {
    const float* tf     = (const float*)d_in[0];
    const float* msa    = (const float*)d_in[1];
    const int*   res    = (const int*)d_in[2];
    const int*   sym    = (const int*)d_in[3];
    const int*   asym   = (const int*)d_in[4];
    const int*   ent    = (const int*)d_in[5];
    const float* w_zi   = (const float*)d_in[6];
    const float* b_zi   = (const float*)d_in[7];
    const float* w_zj   = (const float*)d_in[8];
    const float* b_zj   = (const float*)d_in[9];
    const float* w_m    = (const float*)d_in[10];
    const float* b_m    = (const float*)d_in[11];
    const float* w_msa  = (const float*)d_in[12];
    const float* b_msa  = (const float*)d_in[13];
    const float* w_rel  = (const float*)d_in[14];
    const float* b_rel  = (const float*)d_in[15];

    cudaFuncSetAttribute(uni_kernel, cudaFuncAttributeMaxDynamicSharedMemorySize, U_SMEM);

    pre_kernel<<<96 + 49, 256>>>(tf, w_zi, b_zi, w_zj, b_zj, w_m, b_m, b_msa, w_msa);
    uni_kernel<<<GRID_U, 256, U_SMEM>>>(msa, res, sym, asym, ent, w_rel, b_rel,
                                        (float*)d_out);
}

// round 11
// speedup vs baseline: 1.1922x; 1.0485x over previous
#include <cuda_runtime.h>
#include <cuda_fp16.h>
#include <cstdint>

// Problem constants
#define NRES 768
#define TF   21
#define MSADIM 49
#define CZ   128
#define CM   256
#define MSA_OUT_ELEMS (512u*768u*256u)   // 100663296
#define TOT_ITEMS 15360                  // 5 * 3072
#define GRID_U 444                       // 3 CTAs per SM

// ---------------- device scratch ----------------
__device__ float  g_tfi[NRES * CZ];
__device__ float  g_tfj[NRES * CZ];
__device__ float  g_comb[NRES * CM];
__device__ __half g_wh[48 * CM];         // fp16 weights k=0..47
__device__ float  g_w48[CM];             // fp32 weight row k=48

// ---------------- smem layout per CTA (bytes) ----------------
// W    [48][264h] stride 528   @ 0       (25344)
// raw0 32x49 f32               @ 25344   (6272)
// raw1                         @ 31616   (6272)
// w48  fp32[256]               @ 37888   (1024)
// A_hi [32][56h]  stride 112   @ 38912   (3584)
// stg  16 rows x 1056B         @ 42496   (16896) -> 59392
#define W_STRIDE 528
#define A_STRIDE 112
#define OFF_W    0
#define OFF_RAW0 25344
#define OFF_RAW1 31616
#define OFF_W48  37888
#define OFF_AHI  38912
#define OFF_STG  42496
#define STG_STRIDE 1056
#define U_SMEM   59392

// ---------------- helpers ----------------
__device__ __forceinline__ uint32_t smem_u32(const void* p) {
    uint32_t a;
    asm("{ .reg .u64 t; cvta.to.shared.u64 t, %1; cvt.u32.u64 %0, t; }" : "=r"(a) : "l"(p));
    return a;
}
__device__ __forceinline__ void cp16(uint32_t dst, const void* src) {
    asm volatile("cp.async.cg.shared.global [%0], [%1], 16;" :: "r"(dst), "l"(src) : "memory");
}
__device__ __forceinline__ void cp_commit() {
    asm volatile("cp.async.commit_group;" ::: "memory");
}
__device__ __forceinline__ void cp_wait_all() {
    asm volatile("cp.async.wait_group 0;" ::: "memory");
}

#define LDSM_X4(r, addr) \
    asm volatile("ldmatrix.sync.aligned.m8n8.x4.shared.b16 {%0,%1,%2,%3}, [%4];" \
                 : "=r"((r)[0]), "=r"((r)[1]), "=r"((r)[2]), "=r"((r)[3]) : "r"(addr))
#define LDSM_X4T(r, addr) \
    asm volatile("ldmatrix.sync.aligned.m8n8.x4.trans.shared.b16 {%0,%1,%2,%3}, [%4];" \
                 : "=r"((r)[0]), "=r"((r)[1]), "=r"((r)[2]), "=r"((r)[3]) : "r"(addr))
#define MMAF16(d, a, b0v, b1v) \
    asm volatile("mma.sync.aligned.m16n8k16.row.col.f32.f16.f16.f32 " \
                 "{%0,%1,%2,%3}, {%4,%5,%6,%7}, {%8,%9}, {%0,%1,%2,%3};" \
                 : "+f"((d)[0]), "+f"((d)[1]), "+f"((d)[2]), "+f"((d)[3]) \
                 : "r"((a)[0]), "r"((a)[1]), "r"((a)[2]), "r"((a)[3]), \
                   "r"(b0v), "r"(b1v))

// ---------------- kernel 1: precompute ----------------
__global__ void __launch_bounds__(256) pre_kernel(
        const float* __restrict__ tf,
        const float* __restrict__ wzi, const float* __restrict__ bzi,
        const float* __restrict__ wzj, const float* __restrict__ bzj,
        const float* __restrict__ wm,  const float* __restrict__ bm,
        const float* __restrict__ bmsa, const float* __restrict__ wmsa) {
    int c = threadIdx.x;
    if (blockIdx.x >= 96) {
        int k = blockIdx.x - 96;   // 0..48
        float v = wmsa[k * CM + c];
        if (k < 48) g_wh[k * CM + c] = __float2half_rn(v);
        else        g_w48[c] = v;
        return;
    }
    __shared__ float swm[TF * CM];
    __shared__ float swi[TF * CZ];
    __shared__ float swj[TF * CZ];
    __shared__ float st[8 * TF];

    for (int g = c; g < TF * CM; g += 256) swm[g] = wm[g];
    for (int g = c; g < TF * CZ; g += 256) { swi[g] = wzi[g]; swj[g] = wzj[g]; }
    int i0 = blockIdx.x * 8;
    for (int g = c; g < 8 * TF; g += 256) st[g] = tf[i0 * TF + g];
    __syncthreads();

    float bmv = bm[c] + bmsa[c];
    float bzi_v = (c < CZ) ? bzi[c] : 0.0f;
    float bzj_v = (c < CZ) ? bzj[c] : 0.0f;

#pragma unroll 1
    for (int r = 0; r < 8; r++) {
        const float* t = st + r * TF;
        float am = bmv;
#pragma unroll
        for (int k = 0; k < TF; k++) am += t[k] * swm[k * CM + c];
        g_comb[(i0 + r) * CM + c] = am;

        if (c < CZ) {
            float ai = bzi_v;
            float aj = bzj_v;
#pragma unroll
            for (int k = 0; k < TF; k++) {
                float tv = t[k];
                ai += tv * swi[k * CZ + c];
                aj += tv * swj[k * CZ + c];
            }
            g_tfi[(i0 + r) * CZ + c] = ai;
            g_tfj[(i0 + r) * CZ + c] = aj;
        }
    }
}

// ---------------- kernel 2: unified persistent msa + pair ----------------
// Warp layout: 8 warps, each m32 x n32. B fragments resident in registers.
// Single-term fp16 MMA (A and B both fp16; k=48 exact fp32 fix in epilogue).
__global__ void __launch_bounds__(256, 3) uni_kernel(const float* __restrict__ msa,
                                                     const int* __restrict__ res,
                                                     const int* __restrict__ sym,
                                                     const int* __restrict__ asym,
                                                     const int* __restrict__ ent,
                                                     const float* __restrict__ w_rel,
                                                     const float* __restrict__ b_rel,
                                                     float* __restrict__ out) {
    extern __shared__ char smem[];
    uint32_t sb = smem_u32(smem);
    int tid = threadIdx.x;
    int lane = tid & 31;
    int wid = tid >> 5;
    int bid = blockIdx.x;
    float* msa_out  = out;
    float* pair_out = out + MSA_OUT_ELEMS;

    // stage weights + w48 once
    for (int g = tid; g < 1536; g += 256) {
        int row = g >> 5;
        int c = g & 31;
        cp16(sb + OFF_W + row * W_STRIDE + c * 16, (const char*)g_wh + row * 512 + c * 16);
    }
    if (tid < 64) cp16(sb + OFF_W48 + tid * 16, (const char*)g_w48 + tid * 16);
    // prefetch first msa tile raw
    {
        int wf = bid;
        while (wf < TOT_ITEMS && (wf % 5) == 4) wf += GRID_U;
        if (wf < TOT_ITEMS) {
            int m = (wf / 5) * 4 + (wf % 5);
            const char* src = (const char*)msa + (long)m * 6272;
            for (int g = tid; g < 392; g += 256)
                cp16(sb + OFF_RAW0 + g * 16, src + g * 16);
        }
    }
    cp_commit();

    // per-thread ldmatrix addresses
    uint32_t aoff = (uint32_t)((lane & 15) * A_STRIDE + (lane >> 4) * 16);
    uint32_t ahi_base = sb + OFF_AHI + aoff;
    uint32_t boff = (uint32_t)(((lane & 7) + ((lane >> 3) & 1) * 8) * W_STRIDE +
                               (wid * 32 + (lane >> 4) * 8) * 2);
    uint32_t b_base = sb + OFF_W + boff;
    int qr = lane >> 2;
    int qc = (lane & 3) * 2;
    int msa_cnt = 0;

    const float* s_w48f = (const float*)(smem + OFF_W48);

    // ---- load B fragments ONCE (weights are tile-invariant) ----
    cp_wait_all();
    __syncthreads();
    uint32_t bfr[3][8];
#pragma unroll
    for (int ks = 0; ks < 3; ks++) {
        LDSM_X4T(&bfr[ks][0], b_base + ks * 16 * W_STRIDE);
        LDSM_X4T(&bfr[ks][4], b_base + ks * 16 * W_STRIDE + 32);  // +16 ch
    }

    for (int w = bid; w < TOT_ITEMS; w += GRID_U) {
        if ((w % 5) != 4) {
            // ================= msa tile (32 rows x 256 ch) =================
            int t = (w / 5) * 4 + (w % 5);
            uint32_t raw_cur = (msa_cnt & 1) ? OFF_RAW1 : OFF_RAW0;
            uint32_t raw_nxt = (msa_cnt & 1) ? OFF_RAW0 : OFF_RAW1;
            msa_cnt++;
            const float* rawf = (const float*)(smem + raw_cur);

            cp_wait_all();
            __syncthreads();   // raw ready; prev tile done

            // convert raw -> A fp16 (k<48)
            for (int g = tid; g < 768; g += 256) {
                int row = g / 24;
                int p = g - row * 24;
                float a0 = rawf[row * 49 + 2 * p];
                float a1 = rawf[row * 49 + 2 * p + 1];
                __half h0 = __float2half_rn(a0);
                __half h1 = __float2half_rn(a1);
                uint32_t o = row * A_STRIDE + p * 4;
                *(__half2*)(smem + OFF_AHI + o) = __halves2half2(h0, h1);
            }
            __syncthreads();   // A ready

            // prefetch next msa tile's raw (overlaps MMA)
            {
                int wn = w + GRID_U;
                while (wn < TOT_ITEMS && (wn % 5) == 4) wn += GRID_U;
                if (wn < TOT_ITEMS) {
                    int m2 = (wn / 5) * 4 + (wn % 5);
                    const char* src = (const char*)msa + (long)m2 * 6272;
                    for (int g = tid; g < 392; g += 256)
                        cp16(sb + raw_nxt + g * 16, src + g * 16);
                }
            }
            cp_commit();

            // MMA: 3 k-steps, single term; B resident
            float d[2][4][4];
#pragma unroll
            for (int mt = 0; mt < 2; mt++)
#pragma unroll
                for (int nt = 0; nt < 4; nt++)
#pragma unroll
                    for (int i = 0; i < 4; i++) d[mt][nt][i] = 0.0f;

#pragma unroll
            for (int ks = 0; ks < 3; ks++) {
                uint32_t ak = ks * 32;
                uint32_t af[2][4];
                LDSM_X4(af[0], ahi_base + ak);
                LDSM_X4(af[1], ahi_base + 16 * A_STRIDE + ak);
#pragma unroll
                for (int mt = 0; mt < 2; mt++)
#pragma unroll
                    for (int nt = 0; nt < 4; nt++)
                        MMAF16(d[mt][nt], af[mt], bfr[ks][nt * 2], bfr[ks][nt * 2 + 1]);
            }

            // ---- epilogue: 2 half passes of 16 rows, coalesced ----
            long rowbase = (long)t * 32;
            int n0 = (int)(rowbase % NRES);
#pragma unroll
            for (int p = 0; p < 2; p++) {
                // stage this warp's 32 channels for rows p*16..p*16+15
                {
                    char* stg = smem + OFF_STG;
                    int chb = (wid * 32 + qc) * 4;
#pragma unroll
                    for (int nt = 0; nt < 4; nt++) {
                        *(float2*)(stg + qr * STG_STRIDE + chb + nt * 32) =
                            make_float2(d[p][nt][0], d[p][nt][1]);
                        *(float2*)(stg + (qr + 8) * STG_STRIDE + chb + nt * 32) =
                            make_float2(d[p][nt][2], d[p][nt][3]);
                    }
                }
                __syncthreads();
#pragma unroll
                for (int q = 0; q < 4; q++) {
                    int g = tid + q * 256;
                    int row = g >> 6;        // 0..15
                    int c4 = g & 63;
                    float4 v = *(const float4*)(smem + OFF_STG + row * STG_STRIDE + c4 * 16);
                    float4 w48v = *(const float4*)(s_w48f + c4 * 4);
                    int grow = p * 16 + row;
                    float a48v = rawf[grow * 49 + 48];
                    float4 cb = *(const float4*)(g_comb + (n0 + grow) * CM + c4 * 4);
                    float4 o = make_float4(v.x + a48v * w48v.x + cb.x,
                                           v.y + a48v * w48v.y + cb.y,
                                           v.z + a48v * w48v.z + cb.z,
                                           v.w + a48v * w48v.w + cb.w);
                    *(float4*)(msa_out + (rowbase + grow) * (long)CM + c4 * 4) = o;
                }
                __syncthreads();
            }
        } else {
            // ================= pair tile =================
            int p = w / 5;
            int i = p >> 2;
            int jstart = (p & 3) * 192;
            int jl = tid >> 5;   // 8 j-lanes

            int res_i  = __ldg(res + i);
            int sym_i  = __ldg(sym + i);
            int asym_i = __ldg(asym + i);
            int ent_i  = __ldg(ent + i);

            float4 b4 = ((const float4*)b_rel)[lane];
            float4 ti = ((const float4*)(g_tfi + i * CZ))[lane];
            float4 base4 = make_float4(b4.x + ti.x, b4.y + ti.y, b4.z + ti.z, b4.w + ti.w);
            const float4* W4 = (const float4*)w_rel;
            float4 w66 = W4[66 * 32 + lane];

#pragma unroll 4
            for (int it = 0; it < 24; it++) {
                int j = jstart + it * 8 + jl;
                int rj = __ldg(res + j), sj = __ldg(sym + j), aj = __ldg(asym + j);

                int off = res_i - rj + 32;
                off = min(max(off, 0), 64);
                int pos = (asym_i == aj) ? off : 65;

                int ed = ent_i - sj;
                float entf = (float)ed;

                int cc = sym_i - sj + 2;
                cc = min(max(cc, 0), 4);
                int chain = (ed != 0) ? cc : 5;

                float4 wp = W4[pos * 32 + lane];
                float4 wc = W4[(67 + chain) * 32 + lane];
                float4 tj = ((const float4*)(g_tfj + j * CZ))[lane];

                float4 o;
                o.x = base4.x + wp.x + entf * w66.x + wc.x + tj.x;
                o.y = base4.y + wp.y + entf * w66.y + wc.y + tj.y;
                o.z = base4.z + wp.z + entf * w66.z + wc.z + tj.z;
                o.w = base4.w + wp.w + entf * w66.w + wc.w + tj.w;

                ((float4*)(pair_out + ((size_t)i * NRES + j) * CZ))[lane] = o;
            }
        }
    }
}

// ---------------- launch ----------------
extern "C" void kernel_launch(void* const* d_in, const int* in_sizes, int n_in,
                              void* d_out, int out_size) {
    const float* tf     = (const float*)d_in[0];
    const float* msa    = (const float*)d_in[1];
    const int*   res    = (const int*)d_in[2];
    const int*   sym    = (const int*)d_in[3];
    const int*   asym   = (const int*)d_in[4];
    const int*   ent    = (const int*)d_in[5];
    const float* w_zi   = (const float*)d_in[6];
    const float* b_zi   = (const float*)d_in[7];
    const float* w_zj   = (const float*)d_in[8];
    const float* b_zj   = (const float*)d_in[9];
    const float* w_m    = (const float*)d_in[10];
    const float* b_m    = (const float*)d_in[11];
    const float* w_msa  = (const float*)d_in[12];
    const float* b_msa  = (const float*)d_in[13];
    const float* w_rel  = (const float*)d_in[14];
    const float* b_rel  = (const float*)d_in[15];

    cudaFuncSetAttribute(uni_kernel, cudaFuncAttributeMaxDynamicSharedMemorySize, U_SMEM);

    pre_kernel<<<96 + 49, 256>>>(tf, w_zi, b_zi, w_zj, b_zj, w_m, b_m, b_msa, w_msa);
    uni_kernel<<<GRID_U, 256, U_SMEM>>>(msa, res, sym, asym, ent, w_rel, b_rel,
                                        (float*)d_out);
}

// round 12
// speedup vs baseline: 1.2203x; 1.0236x over previous
#include <cuda_runtime.h>
#include <cuda_fp16.h>
#include <cstdint>

// Problem constants
#define NRES 768
#define TF   21
#define MSADIM 49
#define CZ   128
#define CM   256
#define MSA_OUT_ELEMS (512u*768u*256u)   // 100663296
#define TOT_ITEMS 15360                  // 5 * 3072
#define GRID_U 444                       // 3 CTAs per SM

// ---------------- device scratch ----------------
__device__ float  g_tfi[NRES * CZ];
__device__ float  g_tfj[NRES * CZ];
__device__ float  g_comb[NRES * CM];
__device__ __half g_wh[48 * CM];         // fp16 weights k=0..47
__device__ float  g_w48[CM];             // fp32 weight row k=48
__device__ float  g_w2[396 * CZ];        // W2[pos*6+chain] = w_rel[pos] + w_rel[67+chain]

// ---------------- smem layout per CTA (bytes) ----------------
// W    [48][264h] stride 528   @ 0       (25344)
// raw0 32x49 f32               @ 25344   (6272)
// raw1                         @ 31616   (6272)
// w48  fp32[256]               @ 37888   (1024)
// A_hi [32][56h]  stride 112   @ 38912   (3584)
// stg  16 rows x 1056B         @ 42496   (16896) -> 59392
#define W_STRIDE 528
#define A_STRIDE 112
#define OFF_W    0
#define OFF_RAW0 25344
#define OFF_RAW1 31616
#define OFF_W48  37888
#define OFF_AHI  38912
#define OFF_STG  42496
#define STG_STRIDE 1056
#define U_SMEM   59392

// ---------------- helpers ----------------
__device__ __forceinline__ uint32_t smem_u32(const void* p) {
    uint32_t a;
    asm("{ .reg .u64 t; cvta.to.shared.u64 t, %1; cvt.u32.u64 %0, t; }" : "=r"(a) : "l"(p));
    return a;
}
__device__ __forceinline__ void cp16(uint32_t dst, const void* src) {
    asm volatile("cp.async.cg.shared.global [%0], [%1], 16;" :: "r"(dst), "l"(src) : "memory");
}
__device__ __forceinline__ void cp_commit() {
    asm volatile("cp.async.commit_group;" ::: "memory");
}
__device__ __forceinline__ void cp_wait_all() {
    asm volatile("cp.async.wait_group 0;" ::: "memory");
}

#define LDSM_X4(r, addr) \
    asm volatile("ldmatrix.sync.aligned.m8n8.x4.shared.b16 {%0,%1,%2,%3}, [%4];" \
                 : "=r"((r)[0]), "=r"((r)[1]), "=r"((r)[2]), "=r"((r)[3]) : "r"(addr))
#define LDSM_X4T(r, addr) \
    asm volatile("ldmatrix.sync.aligned.m8n8.x4.trans.shared.b16 {%0,%1,%2,%3}, [%4];" \
                 : "=r"((r)[0]), "=r"((r)[1]), "=r"((r)[2]), "=r"((r)[3]) : "r"(addr))
#define MMAF16(d, a, b0v, b1v) \
    asm volatile("mma.sync.aligned.m16n8k16.row.col.f32.f16.f16.f32 " \
                 "{%0,%1,%2,%3}, {%4,%5,%6,%7}, {%8,%9}, {%0,%1,%2,%3};" \
                 : "+f"((d)[0]), "+f"((d)[1]), "+f"((d)[2]), "+f"((d)[3]) \
                 : "r"((a)[0]), "r"((a)[1]), "r"((a)[2]), "r"((a)[3]), \
                   "r"(b0v), "r"(b1v))

// ---------------- kernel 1: precompute ----------------
// blocks 0..95: per-residue embeddings; 96..144: wconv; 145..540: W2 table.
__global__ void __launch_bounds__(256) pre_kernel(
        const float* __restrict__ tf,
        const float* __restrict__ wzi, const float* __restrict__ bzi,
        const float* __restrict__ wzj, const float* __restrict__ bzj,
        const float* __restrict__ wm,  const float* __restrict__ bm,
        const float* __restrict__ bmsa, const float* __restrict__ wmsa,
        const float* __restrict__ wrel) {
    int c = threadIdx.x;
    if (blockIdx.x >= 145) {
        int widx = blockIdx.x - 145;            // 0..395
        if (c < CZ) {
            int pos = widx / 6;
            int chain = widx - 6 * pos;
            g_w2[widx * CZ + c] = wrel[pos * CZ + c] + wrel[(67 + chain) * CZ + c];
        }
        return;
    }
    if (blockIdx.x >= 96) {
        int k = blockIdx.x - 96;   // 0..48
        float v = wmsa[k * CM + c];
        if (k < 48) g_wh[k * CM + c] = __float2half_rn(v);
        else        g_w48[c] = v;
        return;
    }
    __shared__ float swm[TF * CM];
    __shared__ float swi[TF * CZ];
    __shared__ float swj[TF * CZ];
    __shared__ float st[8 * TF];

    for (int g = c; g < TF * CM; g += 256) swm[g] = wm[g];
    for (int g = c; g < TF * CZ; g += 256) { swi[g] = wzi[g]; swj[g] = wzj[g]; }
    int i0 = blockIdx.x * 8;
    for (int g = c; g < 8 * TF; g += 256) st[g] = tf[i0 * TF + g];
    __syncthreads();

    float bmv = bm[c] + bmsa[c];
    float bzi_v = (c < CZ) ? bzi[c] : 0.0f;
    float bzj_v = (c < CZ) ? bzj[c] : 0.0f;

#pragma unroll 1
    for (int r = 0; r < 8; r++) {
        const float* t = st + r * TF;
        float am = bmv;
#pragma unroll
        for (int k = 0; k < TF; k++) am += t[k] * swm[k * CM + c];
        g_comb[(i0 + r) * CM + c] = am;

        if (c < CZ) {
            float ai = bzi_v;
            float aj = bzj_v;
#pragma unroll
            for (int k = 0; k < TF; k++) {
                float tv = t[k];
                ai += tv * swi[k * CZ + c];
                aj += tv * swj[k * CZ + c];
            }
            g_tfi[(i0 + r) * CZ + c] = ai;
            g_tfj[(i0 + r) * CZ + c] = aj;
        }
    }
}

// ---------------- kernel 2: unified persistent msa + pair ----------------
__global__ void __launch_bounds__(256, 3) uni_kernel(const float* __restrict__ msa,
                                                     const int* __restrict__ res,
                                                     const int* __restrict__ sym,
                                                     const int* __restrict__ asym,
                                                     const int* __restrict__ ent,
                                                     const float* __restrict__ w_rel,
                                                     const float* __restrict__ b_rel,
                                                     float* __restrict__ out) {
    extern __shared__ char smem[];
    uint32_t sb = smem_u32(smem);
    int tid = threadIdx.x;
    int lane = tid & 31;
    int wid = tid >> 5;
    int bid = blockIdx.x;
    float* msa_out  = out;
    float* pair_out = out + MSA_OUT_ELEMS;

    // stage weights + w48 once
    for (int g = tid; g < 1536; g += 256) {
        int row = g >> 5;
        int c = g & 31;
        cp16(sb + OFF_W + row * W_STRIDE + c * 16, (const char*)g_wh + row * 512 + c * 16);
    }
    if (tid < 64) cp16(sb + OFF_W48 + tid * 16, (const char*)g_w48 + tid * 16);
    // prefetch first msa tile raw
    {
        int wf = bid;
        while (wf < TOT_ITEMS && (wf % 5) == 4) wf += GRID_U;
        if (wf < TOT_ITEMS) {
            int m = (wf / 5) * 4 + (wf % 5);
            const char* src = (const char*)msa + (long)m * 6272;
            for (int g = tid; g < 392; g += 256)
                cp16(sb + OFF_RAW0 + g * 16, src + g * 16);
        }
    }
    cp_commit();

    // per-thread ldmatrix addresses
    uint32_t aoff = (uint32_t)((lane & 15) * A_STRIDE + (lane >> 4) * 16);
    uint32_t ahi_base = sb + OFF_AHI + aoff;
    uint32_t boff = (uint32_t)(((lane & 7) + ((lane >> 3) & 1) * 8) * W_STRIDE +
                               (wid * 32 + (lane >> 4) * 8) * 2);
    uint32_t b_base = sb + OFF_W + boff;
    int qr = lane >> 2;
    int qc = (lane & 3) * 2;
    int msa_cnt = 0;

    const float* s_w48f = (const float*)(smem + OFF_W48);

    // ---- load B fragments ONCE (weights are tile-invariant) ----
    cp_wait_all();
    __syncthreads();
    uint32_t bfr[3][8];
#pragma unroll
    for (int ks = 0; ks < 3; ks++) {
        LDSM_X4T(&bfr[ks][0], b_base + ks * 16 * W_STRIDE);
        LDSM_X4T(&bfr[ks][4], b_base + ks * 16 * W_STRIDE + 32);  // +16 ch
    }

    for (int w = bid; w < TOT_ITEMS; w += GRID_U) {
        if ((w % 5) != 4) {
            // ================= msa tile (32 rows x 256 ch) =================
            int t = (w / 5) * 4 + (w % 5);
            uint32_t raw_cur = (msa_cnt & 1) ? OFF_RAW1 : OFF_RAW0;
            uint32_t raw_nxt = (msa_cnt & 1) ? OFF_RAW0 : OFF_RAW1;
            msa_cnt++;
            const float* rawf = (const float*)(smem + raw_cur);

            cp_wait_all();
            __syncthreads();   // raw ready; prev tile done

            // convert raw -> A fp16 (k<48)
            for (int g = tid; g < 768; g += 256) {
                int row = g / 24;
                int p = g - row * 24;
                float a0 = rawf[row * 49 + 2 * p];
                float a1 = rawf[row * 49 + 2 * p + 1];
                __half h0 = __float2half_rn(a0);
                __half h1 = __float2half_rn(a1);
                uint32_t o = row * A_STRIDE + p * 4;
                *(__half2*)(smem + OFF_AHI + o) = __halves2half2(h0, h1);
            }
            __syncthreads();   // A ready

            // prefetch next msa tile's raw (overlaps MMA)
            {
                int wn = w + GRID_U;
                while (wn < TOT_ITEMS && (wn % 5) == 4) wn += GRID_U;
                if (wn < TOT_ITEMS) {
                    int m2 = (wn / 5) * 4 + (wn % 5);
                    const char* src = (const char*)msa + (long)m2 * 6272;
                    for (int g = tid; g < 392; g += 256)
                        cp16(sb + raw_nxt + g * 16, src + g * 16);
                }
            }
            cp_commit();

            // MMA: 3 k-steps, single term; B resident
            float d[2][4][4];
#pragma unroll
            for (int mt = 0; mt < 2; mt++)
#pragma unroll
                for (int nt = 0; nt < 4; nt++)
#pragma unroll
                    for (int i = 0; i < 4; i++) d[mt][nt][i] = 0.0f;

#pragma unroll
            for (int ks = 0; ks < 3; ks++) {
                uint32_t ak = ks * 32;
                uint32_t af[2][4];
                LDSM_X4(af[0], ahi_base + ak);
                LDSM_X4(af[1], ahi_base + 16 * A_STRIDE + ak);
#pragma unroll
                for (int mt = 0; mt < 2; mt++)
#pragma unroll
                    for (int nt = 0; nt < 4; nt++)
                        MMAF16(d[mt][nt], af[mt], bfr[ks][nt * 2], bfr[ks][nt * 2 + 1]);
            }

            // ---- epilogue: 2 half passes of 16 rows, coalesced ----
            long rowbase = (long)t * 32;
            int n0 = (int)(rowbase % NRES);
#pragma unroll
            for (int p = 0; p < 2; p++) {
                {
                    char* stg = smem + OFF_STG;
                    int chb = (wid * 32 + qc) * 4;
#pragma unroll
                    for (int nt = 0; nt < 4; nt++) {
                        *(float2*)(stg + qr * STG_STRIDE + chb + nt * 32) =
                            make_float2(d[p][nt][0], d[p][nt][1]);
                        *(float2*)(stg + (qr + 8) * STG_STRIDE + chb + nt * 32) =
                            make_float2(d[p][nt][2], d[p][nt][3]);
                    }
                }
                __syncthreads();
#pragma unroll
                for (int q = 0; q < 4; q++) {
                    int g = tid + q * 256;
                    int row = g >> 6;        // 0..15
                    int c4 = g & 63;
                    float4 v = *(const float4*)(smem + OFF_STG + row * STG_STRIDE + c4 * 16);
                    float4 w48v = *(const float4*)(s_w48f + c4 * 4);
                    int grow = p * 16 + row;
                    float a48v = rawf[grow * 49 + 48];
                    float4 cb = *(const float4*)(g_comb + (n0 + grow) * CM + c4 * 4);
                    float4 o = make_float4(v.x + a48v * w48v.x + cb.x,
                                           v.y + a48v * w48v.y + cb.y,
                                           v.z + a48v * w48v.z + cb.z,
                                           v.w + a48v * w48v.w + cb.w);
                    *(float4*)(msa_out + (rowbase + grow) * (long)CM + c4 * 4) = o;
                }
                __syncthreads();
            }
        } else {
            // ================= pair tile =================
            int p = w / 5;
            int i = p >> 2;
            int jstart = (p & 3) * 192;
            int jl = tid >> 5;   // 8 j-lanes

            int res_i  = __ldg(res + i);
            int sym_i  = __ldg(sym + i);
            int asym_i = __ldg(asym + i);
            int ent_i  = __ldg(ent + i);

            float4 b4 = ((const float4*)b_rel)[lane];
            float4 ti = ((const float4*)(g_tfi + i * CZ))[lane];
            float4 base4 = make_float4(b4.x + ti.x, b4.y + ti.y, b4.z + ti.z, b4.w + ti.w);
            const float4* W4 = (const float4*)w_rel;
            const float4* W24 = (const float4*)g_w2;
            float4 w66 = W4[66 * 32 + lane];

#pragma unroll 4
            for (int it = 0; it < 24; it++) {
                int j = jstart + it * 8 + jl;
                int rj = __ldg(res + j), sj = __ldg(sym + j), aj = __ldg(asym + j);

                int off = res_i - rj + 32;
                off = min(max(off, 0), 64);
                int pos = (asym_i == aj) ? off : 65;

                int ed = ent_i - sj;
                float entf = (float)ed;

                int cc = sym_i - sj + 2;
                cc = min(max(cc, 0), 4);
                int chain = (ed != 0) ? cc : 5;

                // combined gather: w_rel[pos] + w_rel[67+chain]
                float4 wv = W24[(pos * 6 + chain) * 32 + lane];
                float4 tj = ((const float4*)(g_tfj + j * CZ))[lane];

                float4 o;
                o.x = base4.x + wv.x + entf * w66.x + tj.x;
                o.y = base4.y + wv.y + entf * w66.y + tj.y;
                o.z = base4.z + wv.z + entf * w66.z + tj.z;
                o.w = base4.w + wv.w + entf * w66.w + tj.w;

                ((float4*)(pair_out + ((size_t)i * NRES + j) * CZ))[lane] = o;
            }
        }
    }
}

// ---------------- launch ----------------
extern "C" void kernel_launch(void* const* d_in, const int* in_sizes, int n_in,
                              void* d_out, int out_size) {
    const float* tf     = (const float*)d_in[0];
    const float* msa    = (const float*)d_in[1];
    const int*   res    = (const int*)d_in[2];
    const int*   sym    = (const int*)d_in[3];
    const int*   asym   = (const int*)d_in[4];
    const int*   ent    = (const int*)d_in[5];
    const float* w_zi   = (const float*)d_in[6];
    const float* b_zi   = (const float*)d_in[7];
    const float* w_zj   = (const float*)d_in[8];
    const float* b_zj   = (const float*)d_in[9];
    const float* w_m    = (const float*)d_in[10];
    const float* b_m    = (const float*)d_in[11];
    const float* w_msa  = (const float*)d_in[12];
    const float* b_msa  = (const float*)d_in[13];
    const float* w_rel  = (const float*)d_in[14];
    const float* b_rel  = (const float*)d_in[15];

    cudaFuncSetAttribute(uni_kernel, cudaFuncAttributeMaxDynamicSharedMemorySize, U_SMEM);

    pre_kernel<<<96 + 49 + 396, 256>>>(tf, w_zi, b_zi, w_zj, b_zj, w_m, b_m, b_msa,
                                       w_msa, w_rel);
    uni_kernel<<<GRID_U, 256, U_SMEM>>>(msa, res, sym, asym, ent, w_rel, b_rel,
                                        (float*)d_out);
}